// round 3
// baseline (speedup 1.0000x reference)
#include <cuda_runtime.h>
#include <cuda_bf16.h>

// Problem dimensions (fixed by the dataset)
#define CN 20000
#define CE 160000
#define CP 10000
#define CD 512
#define CS 128
#define CH 1024

// ---------------------------------------------------------------------------
// Static device scratch (no allocations allowed)
// ---------------------------------------------------------------------------
__device__ float g_hidden[(size_t)CE * CH];   // relu(h @ We1 + be1)      [E,1024]
__device__ float g_ef[(size_t)CE * CD];       // e_f                      [E,512]
__device__ float g_a[CE];                     // attention logits
__device__ float g_ex[CE];                    // exp(a - m[dst])
__device__ float g_m[CN];                     // segment max
__device__ float g_den[CN];                   // segment sum of exp
__device__ float g_zf[(size_t)CN * CD];       // z_f                      [N,512]
__device__ float g_newn[(size_t)CN * CD];     // new node features        [N,512]
__device__ float g_ph[(size_t)CP * CD];       // relu(hp @ Wp1 + bp1)     [P,512]

// ---------------------------------------------------------------------------
// Tiled SGEMM: C[M,Nw] = (relu?)(A @ W + bias)
// BM=BN=128, BK=16, 256 threads, 8x8 per thread.
// MODE 0: A = Aplain[M,K] row-major (contiguous)
// MODE 1: A row r = concat(nodef[src[r]], sfeat[r], nodef[dst[r]])   (K=1152)
// MODE 2: pe=pidx[r]; A row r = concat(nodef[src[pe]], sfeat[pe], nodef[dst[pe]])
// MODE 3: A row r = concat(nodef[r], A2[r])                          (K=1024)
// nodef rows are 512 floats; sfeat rows are 128 floats.
// ---------------------------------------------------------------------------
template <int MODE, bool RELU>
__global__ __launch_bounds__(256)
void gemm128(int M, int Nw, int K,
             const float* __restrict__ Aplain,
             const float* __restrict__ nodef,
             const float* __restrict__ sfeat,
             const float* __restrict__ A2,
             const int*   __restrict__ srcI,
             const int*   __restrict__ dstI,
             const int*   __restrict__ pidx,
             const float* __restrict__ W,
             const float* __restrict__ bias,
             float* __restrict__ C)
{
    __shared__ float As[16][132];   // +4 pad: 16B-aligned float4 reads, low-conflict stores
    __shared__ float Bs[16][128];
    __shared__ int   i0s[128], i2s[128], ims[128];

    const int tid = threadIdx.x;
    const int tx  = tid & 15;       // 0..15 -> output cols
    const int ty  = tid >> 4;       // 0..15 -> output rows
    const int colBase = blockIdx.x * 128;
    const int rowBase = blockIdx.y * 128;

    if (MODE == 1 || MODE == 2) {
        if (tid < 128) {
            int row = rowBase + tid;
            if (row >= M) row = M - 1;
            int pe = (MODE == 2) ? pidx[row] : row;
            i0s[tid] = srcI[pe];
            i2s[tid] = dstI[pe];
            ims[tid] = pe;
        }
        __syncthreads();
    }

    float acc[8][8];
#pragma unroll
    for (int i = 0; i < 8; i++)
#pragma unroll
        for (int j = 0; j < 8; j++) acc[i][j] = 0.f;

    const int numK = K >> 4;
    for (int kt = 0; kt < numK; kt++) {
        const int k0 = kt << 4;

        // ---- load A tile (gathered), store transposed into As[k][m] ----
#pragma unroll
        for (int ls = 0; ls < 2; ls++) {
            int s  = tid + ls * 256;          // 0..511
            int m  = s >> 2;                  // 0..127
            int kq = (s & 3) << 2;            // 0,4,8,12
            float4 v;
            if (MODE == 0) {
                int row = rowBase + m; if (row >= M) row = M - 1;
                v = *(const float4*)(Aplain + (size_t)row * K + k0 + kq);
            } else if (MODE == 3) {
                int row = rowBase + m; if (row >= M) row = M - 1;
                int k = k0 + kq;
                const float* p = (k < 512) ? (nodef + (size_t)row * 512 + k)
                                           : (A2    + (size_t)row * 512 + (k - 512));
                v = *(const float4*)p;
            } else {
                int k = k0 + kq;
                const float* p;
                if (k < 512)       p = nodef + (size_t)i0s[m] * 512 + k;
                else if (k < 640)  p = sfeat + (size_t)ims[m] * 128 + (k - 512);
                else               p = nodef + (size_t)i2s[m] * 512 + (k - 640);
                v = *(const float4*)p;
            }
            As[kq + 0][m] = v.x;
            As[kq + 1][m] = v.y;
            As[kq + 2][m] = v.z;
            As[kq + 3][m] = v.w;
        }

        // ---- load B tile (coalesced float4) ----
#pragma unroll
        for (int ls = 0; ls < 2; ls++) {
            int s  = tid + ls * 256;
            int kk = s >> 5;                  // 0..15
            int nq = (s & 31) << 2;           // 0..124
            *(float4*)&Bs[kk][nq] =
                *(const float4*)(W + (size_t)(k0 + kk) * Nw + colBase + nq);
        }
        __syncthreads();

        // ---- compute 8x8 outer products over BK=16 ----
#pragma unroll
        for (int k = 0; k < 16; k++) {
            float4 a0 = *(const float4*)&As[k][ty * 8];
            float4 a1 = *(const float4*)&As[k][ty * 8 + 4];
            float4 b0 = *(const float4*)&Bs[k][tx * 8];
            float4 b1 = *(const float4*)&Bs[k][tx * 8 + 4];
            float av[8] = {a0.x, a0.y, a0.z, a0.w, a1.x, a1.y, a1.z, a1.w};
            float bv[8] = {b0.x, b0.y, b0.z, b0.w, b1.x, b1.y, b1.z, b1.w};
#pragma unroll
            for (int i = 0; i < 8; i++)
#pragma unroll
                for (int j = 0; j < 8; j++)
                    acc[i][j] += av[i] * bv[j];
        }
        __syncthreads();
    }

    // ---- epilogue: bias (+relu), row-guarded float4 stores ----
#pragma unroll
    for (int i = 0; i < 8; i++) {
        int row = rowBase + ty * 8 + i;
        if (row < M) {
#pragma unroll
            for (int j = 0; j < 8; j += 4) {
                int col = colBase + tx * 8 + j;
                float4 o;
                o.x = acc[i][j + 0] + bias[col + 0];
                o.y = acc[i][j + 1] + bias[col + 1];
                o.z = acc[i][j + 2] + bias[col + 2];
                o.w = acc[i][j + 3] + bias[col + 3];
                if (RELU) {
                    o.x = fmaxf(o.x, 0.f); o.y = fmaxf(o.y, 0.f);
                    o.z = fmaxf(o.z, 0.f); o.w = fmaxf(o.w, 0.f);
                }
                *(float4*)(C + (size_t)row * Nw + col) = o;
            }
        }
    }
}

// ---------------------------------------------------------------------------
// Segment softmax + scatter
// ---------------------------------------------------------------------------
__device__ __forceinline__ void atomicMaxFloat(float* addr, float value) {
    // Works for all finite floats and the -inf init: int-max for >=0,
    // uint-min for <0 (negative floats reverse-order under uint compare).
    if (value >= 0.f)
        atomicMax((int*)addr, __float_as_int(value));
    else
        atomicMin((unsigned int*)addr, __float_as_uint(value));
}

__global__ void init_kernel(float* __restrict__ m, float* __restrict__ den,
                            float* __restrict__ zf)
{
    size_t i = (size_t)blockIdx.x * 256 + threadIdx.x;
    if (i < (size_t)CN * CD) zf[i] = 0.f;
    if (i < CN) { m[i] = __int_as_float(0xff800000); den[i] = 0.f; }
}

// a[e] = dot(e_f[e], Wa) + ba ; atomic segment max into m[dst[e]]
__global__ void edge_logit_kernel(const float* __restrict__ ef,
                                  const float* __restrict__ Wa,
                                  const float* __restrict__ ba,
                                  const int*   __restrict__ dst,
                                  float* __restrict__ a,
                                  float* __restrict__ m)
{
    int e    = blockIdx.x * 8 + (threadIdx.x >> 5);
    int lane = threadIdx.x & 31;
    if (e >= CE) return;
    const float4* row = (const float4*)(ef + (size_t)e * CD);
    const float4* w   = (const float4*)Wa;
    float s = 0.f;
#pragma unroll
    for (int i = 0; i < 4; i++) {
        float4 v  = row[lane + i * 32];
        float4 wv = w[lane + i * 32];
        s += v.x * wv.x + v.y * wv.y + v.z * wv.z + v.w * wv.w;
    }
#pragma unroll
    for (int o = 16; o; o >>= 1) s += __shfl_xor_sync(0xffffffffu, s, o);
    if (lane == 0) {
        s += ba[0];
        a[e] = s;
        atomicMaxFloat(&m[dst[e]], s);
    }
}

__global__ void edge_exp_kernel(const float* __restrict__ a,
                                const int*   __restrict__ dst,
                                const float* __restrict__ m,
                                float* __restrict__ ex,
                                float* __restrict__ den)
{
    int e = blockIdx.x * 256 + threadIdx.x;
    if (e >= CE) return;
    int d = dst[e];
    float v = expf(a[e] - m[d]);
    ex[e] = v;
    atomicAdd(&den[d], v);
}

// z_f[dst[e]] += alpha_e * (n_f[src[e]] + e_f[e]); one 128-thread block per edge
__global__ void scatter_z_kernel(const float* __restrict__ nf,
                                 const float* __restrict__ ef,
                                 const int*   __restrict__ src,
                                 const int*   __restrict__ dst,
                                 const float* __restrict__ ex,
                                 const float* __restrict__ den,
                                 float* __restrict__ zf)
{
    int e = blockIdx.x;
    int t = threadIdx.x;            // 0..127 -> 4 floats each
    int d = dst[e], s = src[e];
    float alpha = ex[e] / den[d];
    float4 v = *(const float4*)(nf + (size_t)s * CD + t * 4);
    float4 w = *(const float4*)(ef + (size_t)e * CD + t * 4);
    float* zp = zf + (size_t)d * CD + t * 4;
    atomicAdd(zp + 0, alpha * (v.x + w.x));
    atomicAdd(zp + 1, alpha * (v.y + w.y));
    atomicAdd(zp + 2, alpha * (v.z + w.z));
    atomicAdd(zp + 3, alpha * (v.w + w.w));
}

// pred[p] = dot(ph[p], Wp2) + bp2
__global__ void pred_kernel(const float* __restrict__ ph,
                            const float* __restrict__ Wp2,
                            const float* __restrict__ bp2,
                            float* __restrict__ out)
{
    int p    = blockIdx.x * 8 + (threadIdx.x >> 5);
    int lane = threadIdx.x & 31;
    if (p >= CP) return;
    const float4* row = (const float4*)(ph + (size_t)p * CD);
    const float4* w   = (const float4*)Wp2;
    float s = 0.f;
#pragma unroll
    for (int i = 0; i < 4; i++) {
        float4 v  = row[lane + i * 32];
        float4 wv = w[lane + i * 32];
        s += v.x * wv.x + v.y * wv.y + v.z * wv.z + v.w * wv.w;
    }
#pragma unroll
    for (int o = 16; o; o >>= 1) s += __shfl_xor_sync(0xffffffffu, s, o);
    if (lane == 0) out[p] = s + bp2[0];
}

// ---------------------------------------------------------------------------
// Launch
// ---------------------------------------------------------------------------
extern "C" void kernel_launch(void* const* d_in, const int* in_sizes, int n_in,
                              void* d_out, int out_size)
{
    const float* n_f  = (const float*)d_in[0];
    const float* s_f  = (const float*)d_in[1];
    const float* We1  = (const float*)d_in[2];
    const float* be1  = (const float*)d_in[3];
    const float* We2  = (const float*)d_in[4];
    const float* be2  = (const float*)d_in[5];
    const float* Wa   = (const float*)d_in[6];
    const float* ba   = (const float*)d_in[7];
    const float* Wn   = (const float*)d_in[8];
    const float* bn   = (const float*)d_in[9];
    const float* Wp1  = (const float*)d_in[10];
    const float* bp1  = (const float*)d_in[11];
    const float* Wp2  = (const float*)d_in[12];
    const float* bp2  = (const float*)d_in[13];
    const int*   src  = (const int*)d_in[14];
    const int*   dst  = (const int*)d_in[15];
    const int*   pidx = (const int*)d_in[16];
    float* out = (float*)d_out;

    float *hiddenP, *efP, *aP, *exP, *mP, *denP, *zfP, *newnP, *phP;
    cudaGetSymbolAddress((void**)&hiddenP, g_hidden);
    cudaGetSymbolAddress((void**)&efP,     g_ef);
    cudaGetSymbolAddress((void**)&aP,      g_a);
    cudaGetSymbolAddress((void**)&exP,     g_ex);
    cudaGetSymbolAddress((void**)&mP,      g_m);
    cudaGetSymbolAddress((void**)&denP,    g_den);
    cudaGetSymbolAddress((void**)&zfP,     g_zf);
    cudaGetSymbolAddress((void**)&newnP,   g_newn);
    cudaGetSymbolAddress((void**)&phP,     g_ph);

    // 0) init m=-inf, den=0, z_f=0
    {
        int total = CN * CD;                       // 10,240,000
        init_kernel<<<(total + 255) / 256, 256>>>(mP, denP, zfP);
    }

    // 1) hidden = relu(concat(n_f[src], s_f, n_f[dst]) @ We1 + be1)   [E,1024]
    gemm128<1, true><<<dim3(CH / 128, CE / 128), 256>>>(
        CE, CH, 2 * CD + CS, nullptr, n_f, s_f, nullptr, src, dst, nullptr,
        We1, be1, hiddenP);

    // 2) e_f = hidden @ We2 + be2                                     [E,512]
    gemm128<0, false><<<dim3(CD / 128, CE / 128), 256>>>(
        CE, CD, CH, hiddenP, nullptr, nullptr, nullptr, nullptr, nullptr, nullptr,
        We2, be2, efP);

    // 3) a = e_f @ Wa + ba ; segment max
    edge_logit_kernel<<<CE / 8, 256>>>(efP, Wa, ba, dst, aP, mP);

    // 4) ex = exp(a - m[dst]) ; segment sum
    edge_exp_kernel<<<(CE + 255) / 256, 256>>>(aP, dst, mP, exP, denP);

    // 5) z_f scatter-add
    scatter_z_kernel<<<CE, 128>>>(n_f, efP, src, dst, exP, denP, zfP);

    // 6) new_n = concat(n_f, z_f) @ Wn + bn                           [N,512]
    gemm128<3, false><<<dim3(CD / 128, (CN + 127) / 128), 256>>>(
        CN, CD, 2 * CD, nullptr, n_f, nullptr, zfP, nullptr, nullptr, nullptr,
        Wn, bn, newnP);

    // 7) ph = relu(concat(new_n[src[pe]], s_f[pe], new_n[dst[pe]]) @ Wp1 + bp1)
    gemm128<2, true><<<dim3(CD / 128, (CP + 127) / 128), 256>>>(
        CP, CD, 2 * CD + CS, nullptr, newnP, s_f, nullptr, src, dst, pidx,
        Wp1, bp1, phP);

    // 8) pred = ph @ Wp2 + bp2
    pred_kernel<<<CP / 8, 256>>>(phP, Wp2, bp2, out);
}

// round 5
// speedup vs baseline: 1.6933x; 1.6933x over previous
#include <cuda_runtime.h>
#include <cuda_fp16.h>
#include <cstdint>

// Problem dimensions (fixed by the dataset)
#define CN 20000
#define CE 160000
#define CP 10000
#define CD 512
#define CS 128
#define CH 1024
#define K1 (2*CD+CS)   // 1152

// ---------------------------------------------------------------------------
// Static device scratch (no allocations allowed)
// ---------------------------------------------------------------------------
__device__ __half g_hidhi[(size_t)CE * CH];   // relu(h@We1+be1) hi  [E,1024]
__device__ __half g_hidlo[(size_t)CE * CH];
__device__ __half g_w1hi[(size_t)CH * K1];    // We1^T hi  [1024,1152]
__device__ __half g_w1lo[(size_t)CH * K1];
__device__ __half g_w2hi[(size_t)CD * CH];    // We2^T hi  [512,1024]
__device__ __half g_w2lo[(size_t)CD * CH];
__device__ float g_ef[(size_t)CE * CD];       // e_f  [E,512]
__device__ float g_a[CE];
__device__ float g_ex[CE];
__device__ float g_m[CN];
__device__ float g_den[CN];
__device__ float g_zf[(size_t)CN * CD];
__device__ float g_newn[(size_t)CN * CD];
__device__ float g_ph[(size_t)CP * CD];

// ---------------------------------------------------------------------------
// mma.sync helpers (sm_80-class instructions; assemble on plain sm_100)
// ---------------------------------------------------------------------------
__device__ __forceinline__ uint32_t smem_u32(const void* p) {
    uint32_t a;
    asm("{ .reg .u64 t; cvta.to.shared.u64 t, %1; cvt.u32.u64 %0, t; }" : "=r"(a) : "l"(p));
    return a;
}

__device__ __forceinline__ void ldsm_x4(uint32_t* r, uint32_t addr) {
    asm volatile("ldmatrix.sync.aligned.m8n8.x4.shared.b16 {%0,%1,%2,%3}, [%4];"
                 : "=r"(r[0]), "=r"(r[1]), "=r"(r[2]), "=r"(r[3]) : "r"(addr));
}

__device__ __forceinline__ void mma16816(float* d, const uint32_t* a,
                                         const uint32_t b0, const uint32_t b1) {
    asm volatile(
        "mma.sync.aligned.m16n8k16.row.col.f32.f16.f16.f32 "
        "{%0,%1,%2,%3}, {%4,%5,%6,%7}, {%8,%9}, {%0,%1,%2,%3};"
        : "+f"(d[0]), "+f"(d[1]), "+f"(d[2]), "+f"(d[3])
        : "r"(a[0]), "r"(a[1]), "r"(a[2]), "r"(a[3]), "r"(b0), "r"(b1));
}

__device__ __forceinline__ uint32_t packh(__half a, __half b) {
    return (uint32_t)__half_as_ushort(a) | ((uint32_t)__half_as_ushort(b) << 16);
}
__device__ __forceinline__ void splitH2(float x0, float x1, uint32_t& hi, uint32_t& lo) {
    __half h0 = __float2half_rn(x0);
    __half h1 = __float2half_rn(x1);
    float r0 = x0 - __half2float(h0);
    float r1 = x1 - __half2float(h1);
    hi = packh(h0, h1);
    lo = packh(__float2half_rn(r0), __float2half_rn(r1));
}

// ---------------------------------------------------------------------------
// Split-fp16 3-pass tensor GEMM.  C[M,Ntot] = act(A @ W + bias)
// MODE 0: A row r = concat(n_f[src[r]], s_f[r], n_f[dst[r]]) fp32 gather,
//         split to fp16 hi/lo on the fly; epilogue = relu -> fp16 hi/lo pair.
// MODE 1: A = pre-split fp16 hi/lo [M,Ktot]; epilogue = fp32 + bias.
// B: pre-transposed pre-split fp16 [Ntot][Ktot] (k-contiguous = "col" operand).
// CTA tile 128x128, BK=32, 8 warps (4 m x 2 n), warp tile 32x64.
// smem rows padded to 80B -> conflict-free ldmatrix.
// ---------------------------------------------------------------------------
#define ROWB 80
#define MATB (128 * ROWB)               // 10240 B per matrix buffer
#define SMEM_MMA (1024 + 8 * MATB)      // indices + 2 stages x 4 matrices

template <int MODE>
__global__ void __launch_bounds__(256, 1)
mma_gemm(int Ntot, int Ktot,
         const float* __restrict__ n_f, const float* __restrict__ s_f,
         const int* __restrict__ srcI, const int* __restrict__ dstI,
         const __half* __restrict__ Ahi, const __half* __restrict__ Alo,
         const __half* __restrict__ Bhi, const __half* __restrict__ Blo,
         const float* __restrict__ bias,
         __half* __restrict__ outHi, __half* __restrict__ outLo,
         float* __restrict__ outF)
{
    extern __shared__ char smem[];
    int* i0s = (int*)smem;
    int* i2s = i0s + 128;
    char* bufs = smem + 1024;
    const uint32_t sbufs = smem_u32(smem) + 1024;

    const int tid = threadIdx.x;
    const int wid = tid >> 5, lane = tid & 31;
    const int warpM = wid & 3, warpN = wid >> 2;
    const int rowBase = blockIdx.y * 128;
    const int colBase = blockIdx.x * 128;
    const int lrow = tid >> 1, lhalf = tid & 1;   // global-load coords

    if (MODE == 0) {
        if (tid < 128) {
            i0s[tid] = srcI[rowBase + tid];
            i2s[tid] = dstI[rowBase + tid];
        }
        __syncthreads();
    }

    float acc[2][8][4];
#pragma unroll
    for (int a = 0; a < 2; a++)
#pragma unroll
        for (int b = 0; b < 8; b++)
#pragma unroll
            for (int c = 0; c < 4; c++) acc[a][b][c] = 0.f;

    // load registers (one chunk in flight)
    float fA[16];
    uint4 a_h[2], a_l[2], b_h[2], b_l[2];

    const int NCH = Ktot >> 5;   // BK=32 chunks

    auto loadRegs = [&](int c) {
        const int kk = (c << 5) + lhalf * 16;
        {   // B: [N][K] fp16, 16 halves = 2x uint4
            size_t off = (size_t)(colBase + lrow) * Ktot + kk;
            const uint4* pb = (const uint4*)(Bhi + off);
            const uint4* pl = (const uint4*)(Blo + off);
            b_h[0] = pb[0]; b_h[1] = pb[1];
            b_l[0] = pl[0]; b_l[1] = pl[1];
        }
        if (MODE == 0) {
            const float* p;
            if (kk < CD)           p = n_f + (size_t)i0s[lrow] * CD + kk;
            else if (kk < CD + CS) p = s_f + (size_t)(rowBase + lrow) * CS + (kk - CD);
            else                   p = n_f + (size_t)i2s[lrow] * CD + (kk - CD - CS);
#pragma unroll
            for (int j = 0; j < 4; j++) ((float4*)fA)[j] = ((const float4*)p)[j];
        } else {
            size_t off = (size_t)(rowBase + lrow) * Ktot + kk;
            const uint4* ph = (const uint4*)(Ahi + off);
            const uint4* pl = (const uint4*)(Alo + off);
            a_h[0] = ph[0]; a_h[1] = ph[1];
            a_l[0] = pl[0]; a_l[1] = pl[1];
        }
    };

    auto storeRegs = [&](int buf) {
        const uint32_t ro = (uint32_t)lrow * ROWB + lhalf * 32;
        char* pAh = bufs + (buf * 4 + 0) * MATB + ro;
        char* pAl = bufs + (buf * 4 + 1) * MATB + ro;
        char* pBh = bufs + (buf * 4 + 2) * MATB + ro;
        char* pBl = bufs + (buf * 4 + 3) * MATB + ro;
        if (MODE == 0) {
            uint32_t hi[8], lo[8];
#pragma unroll
            for (int j = 0; j < 8; j++) splitH2(fA[2 * j], fA[2 * j + 1], hi[j], lo[j]);
            *(uint4*)pAh        = make_uint4(hi[0], hi[1], hi[2], hi[3]);
            *(uint4*)(pAh + 16) = make_uint4(hi[4], hi[5], hi[6], hi[7]);
            *(uint4*)pAl        = make_uint4(lo[0], lo[1], lo[2], lo[3]);
            *(uint4*)(pAl + 16) = make_uint4(lo[4], lo[5], lo[6], lo[7]);
        } else {
            *(uint4*)pAh = a_h[0]; *(uint4*)(pAh + 16) = a_h[1];
            *(uint4*)pAl = a_l[0]; *(uint4*)(pAl + 16) = a_l[1];
        }
        *(uint4*)pBh = b_h[0]; *(uint4*)(pBh + 16) = b_h[1];
        *(uint4*)pBl = b_l[0]; *(uint4*)(pBl + 16) = b_l[1];
    };

    // prologue
    loadRegs(0);
    storeRegs(0);
    if (NCH > 1) loadRegs(1);
    __syncthreads();

    const uint32_t lsel = (uint32_t)(lane & 15) * ROWB + (lane >> 4) * 16;

    for (int c = 0; c < NCH; c++) {
        const int buf = c & 1;
        if (c + 1 < NCH) storeRegs(buf ^ 1);     // chunk c+1 -> other stage
        if (c + 2 < NCH) loadRegs(c + 2);        // prefetch next-next

        // compute on stage `buf`
        const uint32_t aHiB = sbufs + (buf * 4 + 0) * MATB;
        const uint32_t aLoB = sbufs + (buf * 4 + 1) * MATB;
        const uint32_t bHiB = sbufs + (buf * 4 + 2) * MATB;
        const uint32_t bLoB = sbufs + (buf * 4 + 3) * MATB;
#pragma unroll
        for (int s = 0; s < 2; s++) {
            const uint32_t kb = s * 32;
            uint32_t ah[2][4], al[2][4];
#pragma unroll
            for (int t = 0; t < 2; t++) {
                uint32_t off = (uint32_t)(warpM * 32 + t * 16) * ROWB + kb + lsel;
                ldsm_x4(ah[t], aHiB + off);
                ldsm_x4(al[t], aLoB + off);
            }
            uint32_t bh[4][4], bl[4][4];
#pragma unroll
            for (int i = 0; i < 4; i++) {
                uint32_t off = (uint32_t)(warpN * 64 + i * 16) * ROWB + kb + lsel;
                ldsm_x4(bh[i], bHiB + off);
                ldsm_x4(bl[i], bLoB + off);
            }
#pragma unroll
            for (int mt = 0; mt < 2; mt++)
#pragma unroll
                for (int nt = 0; nt < 8; nt++) {
                    const int i = nt >> 1, sel = nt & 1;
                    mma16816(acc[mt][nt], ah[mt], bh[i][sel], bh[i][2 + sel]);
                    mma16816(acc[mt][nt], ah[mt], bl[i][sel], bl[i][2 + sel]);
                    mma16816(acc[mt][nt], al[mt], bh[i][sel], bh[i][2 + sel]);
                }
        }
        __syncthreads();
    }

    // epilogue: c0/c1 -> row t/4, c2/c3 -> row t/4+8; cols 2*(t%4)+{0,1}
#pragma unroll
    for (int mt = 0; mt < 2; mt++) {
        const int r0 = rowBase + warpM * 32 + mt * 16 + (lane >> 2);
#pragma unroll
        for (int nt = 0; nt < 8; nt++) {
            const int c0 = colBase + warpN * 64 + nt * 8 + (lane & 3) * 2;
            const float b0 = bias[c0], b1 = bias[c0 + 1];
            float v00 = acc[mt][nt][0] + b0, v01 = acc[mt][nt][1] + b1;
            float v10 = acc[mt][nt][2] + b0, v11 = acc[mt][nt][3] + b1;
            if (MODE == 0) {
                v00 = fmaxf(v00, 0.f); v01 = fmaxf(v01, 0.f);
                v10 = fmaxf(v10, 0.f); v11 = fmaxf(v11, 0.f);
                uint32_t h, l;
                splitH2(v00, v01, h, l);
                *(uint32_t*)(outHi + (size_t)r0 * Ntot + c0) = h;
                *(uint32_t*)(outLo + (size_t)r0 * Ntot + c0) = l;
                splitH2(v10, v11, h, l);
                *(uint32_t*)(outHi + (size_t)(r0 + 8) * Ntot + c0) = h;
                *(uint32_t*)(outLo + (size_t)(r0 + 8) * Ntot + c0) = l;
            } else {
                float2 o0 = make_float2(v00, v01);
                float2 o1 = make_float2(v10, v11);
                *(float2*)(outF + (size_t)r0 * Ntot + c0) = o0;
                *(float2*)(outF + (size_t)(r0 + 8) * Ntot + c0) = o1;
            }
        }
    }
}

// ---------------------------------------------------------------------------
// Weight prep: W[K][N] fp32 -> Wt hi/lo [N][K] fp16 (tiled transpose)
// ---------------------------------------------------------------------------
__global__ void transpose_split(const float* __restrict__ W,
                                __half* __restrict__ hi,
                                __half* __restrict__ lo,
                                int K, int N)
{
    __shared__ float t[32][33];
    const int nb = blockIdx.x * 32, kb = blockIdx.y * 32;
    const int x = threadIdx.x, y = threadIdx.y;   // (32,8)
#pragma unroll
    for (int i = 0; i < 32; i += 8)
        t[y + i][x] = W[(size_t)(kb + y + i) * N + nb + x];
    __syncthreads();
#pragma unroll
    for (int i = 0; i < 32; i += 8) {
        float v = t[x][y + i];
        __half h = __float2half_rn(v);
        size_t o = (size_t)(nb + y + i) * K + kb + x;
        hi[o] = h;
        lo[o] = __float2half_rn(v - __half2float(h));
    }
}

// ---------------------------------------------------------------------------
// fp32 tiled SGEMM (node/pred GEMMs; 33 GF total)
// MODE 2: pe=pidx[r]; A row r = concat(nodef[src[pe]], sfeat[pe], nodef[dst[pe]])
// MODE 3: A row r = concat(nodef[r], A2[r])
// ---------------------------------------------------------------------------
template <int MODE, bool RELU>
__global__ __launch_bounds__(256)
void gemm128(int M, int Nw, int K,
             const float* __restrict__ nodef,
             const float* __restrict__ sfeat,
             const float* __restrict__ A2,
             const int*   __restrict__ srcI,
             const int*   __restrict__ dstI,
             const int*   __restrict__ pidx,
             const float* __restrict__ W,
             const float* __restrict__ bias,
             float* __restrict__ C)
{
    __shared__ float As[16][132];
    __shared__ float Bs[16][128];
    __shared__ int   i0s[128], i2s[128], ims[128];

    const int tid = threadIdx.x;
    const int tx  = tid & 15;
    const int ty  = tid >> 4;
    const int colBase = blockIdx.x * 128;
    const int rowBase = blockIdx.y * 128;

    if (MODE == 2) {
        if (tid < 128) {
            int row = rowBase + tid;
            if (row >= M) row = M - 1;
            int pe = pidx[row];
            i0s[tid] = srcI[pe];
            i2s[tid] = dstI[pe];
            ims[tid] = pe;
        }
        __syncthreads();
    }

    float acc[8][8];
#pragma unroll
    for (int i = 0; i < 8; i++)
#pragma unroll
        for (int j = 0; j < 8; j++) acc[i][j] = 0.f;

    const int numK = K >> 4;
    for (int kt = 0; kt < numK; kt++) {
        const int k0 = kt << 4;
#pragma unroll
        for (int ls = 0; ls < 2; ls++) {
            int s  = tid + ls * 256;
            int m  = s >> 2;
            int kq = (s & 3) << 2;
            float4 v;
            if (MODE == 3) {
                int row = rowBase + m; if (row >= M) row = M - 1;
                int k = k0 + kq;
                const float* p = (k < 512) ? (nodef + (size_t)row * 512 + k)
                                           : (A2    + (size_t)row * 512 + (k - 512));
                v = *(const float4*)p;
            } else {
                int k = k0 + kq;
                const float* p;
                if (k < 512)       p = nodef + (size_t)i0s[m] * 512 + k;
                else if (k < 640)  p = sfeat + (size_t)ims[m] * 128 + (k - 512);
                else               p = nodef + (size_t)i2s[m] * 512 + (k - 640);
                v = *(const float4*)p;
            }
            As[kq + 0][m] = v.x;
            As[kq + 1][m] = v.y;
            As[kq + 2][m] = v.z;
            As[kq + 3][m] = v.w;
        }
#pragma unroll
        for (int ls = 0; ls < 2; ls++) {
            int s  = tid + ls * 256;
            int kk = s >> 5;
            int nq = (s & 31) << 2;
            *(float4*)&Bs[kk][nq] =
                *(const float4*)(W + (size_t)(k0 + kk) * Nw + colBase + nq);
        }
        __syncthreads();
#pragma unroll
        for (int k = 0; k < 16; k++) {
            float4 a0 = *(const float4*)&As[k][ty * 8];
            float4 a1 = *(const float4*)&As[k][ty * 8 + 4];
            float4 b0 = *(const float4*)&Bs[k][tx * 8];
            float4 b1 = *(const float4*)&Bs[k][tx * 8 + 4];
            float av[8] = {a0.x, a0.y, a0.z, a0.w, a1.x, a1.y, a1.z, a1.w};
            float bv[8] = {b0.x, b0.y, b0.z, b0.w, b1.x, b1.y, b1.z, b1.w};
#pragma unroll
            for (int i = 0; i < 8; i++)
#pragma unroll
                for (int j = 0; j < 8; j++)
                    acc[i][j] += av[i] * bv[j];
        }
        __syncthreads();
    }

#pragma unroll
    for (int i = 0; i < 8; i++) {
        int row = rowBase + ty * 8 + i;
        if (row < M) {
#pragma unroll
            for (int j = 0; j < 8; j += 4) {
                int col = colBase + tx * 8 + j;
                float4 o;
                o.x = acc[i][j + 0] + bias[col + 0];
                o.y = acc[i][j + 1] + bias[col + 1];
                o.z = acc[i][j + 2] + bias[col + 2];
                o.w = acc[i][j + 3] + bias[col + 3];
                if (RELU) {
                    o.x = fmaxf(o.x, 0.f); o.y = fmaxf(o.y, 0.f);
                    o.z = fmaxf(o.z, 0.f); o.w = fmaxf(o.w, 0.f);
                }
                *(float4*)(C + (size_t)row * Nw + col) = o;
            }
        }
    }
}

// ---------------------------------------------------------------------------
// Segment softmax + scatter
// ---------------------------------------------------------------------------
__device__ __forceinline__ void atomicMaxFloat(float* addr, float value) {
    if (value >= 0.f)
        atomicMax((int*)addr, __float_as_int(value));
    else
        atomicMin((unsigned int*)addr, __float_as_uint(value));
}

__global__ void init_kernel(float* __restrict__ m, float* __restrict__ den,
                            float* __restrict__ zf)
{
    size_t i = (size_t)blockIdx.x * 256 + threadIdx.x;
    if (i < (size_t)CN * CD) zf[i] = 0.f;
    if (i < CN) { m[i] = __int_as_float(0xff800000); den[i] = 0.f; }
}

__global__ void edge_logit_kernel(const float* __restrict__ ef,
                                  const float* __restrict__ Wa,
                                  const float* __restrict__ ba,
                                  const int*   __restrict__ dst,
                                  float* __restrict__ a,
                                  float* __restrict__ m)
{
    int e    = blockIdx.x * 8 + (threadIdx.x >> 5);
    int lane = threadIdx.x & 31;
    if (e >= CE) return;
    const float4* row = (const float4*)(ef + (size_t)e * CD);
    const float4* w   = (const float4*)Wa;
    float s = 0.f;
#pragma unroll
    for (int i = 0; i < 4; i++) {
        float4 v  = row[lane + i * 32];
        float4 wv = w[lane + i * 32];
        s += v.x * wv.x + v.y * wv.y + v.z * wv.z + v.w * wv.w;
    }
#pragma unroll
    for (int o = 16; o; o >>= 1) s += __shfl_xor_sync(0xffffffffu, s, o);
    if (lane == 0) {
        s += ba[0];
        a[e] = s;
        atomicMaxFloat(&m[dst[e]], s);
    }
}

__global__ void edge_exp_kernel(const float* __restrict__ a,
                                const int*   __restrict__ dst,
                                const float* __restrict__ m,
                                float* __restrict__ ex,
                                float* __restrict__ den)
{
    int e = blockIdx.x * 256 + threadIdx.x;
    if (e >= CE) return;
    int d = dst[e];
    float v = expf(a[e] - m[d]);
    ex[e] = v;
    atomicAdd(&den[d], v);
}

__global__ void scatter_z_kernel(const float* __restrict__ nf,
                                 const float* __restrict__ ef,
                                 const int*   __restrict__ src,
                                 const int*   __restrict__ dst,
                                 const float* __restrict__ ex,
                                 const float* __restrict__ den,
                                 float* __restrict__ zf)
{
    int e = blockIdx.x;
    int t = threadIdx.x;
    int d = dst[e], s = src[e];
    float alpha = ex[e] / den[d];
    float4 v = *(const float4*)(nf + (size_t)s * CD + t * 4);
    float4 w = *(const float4*)(ef + (size_t)e * CD + t * 4);
    float* zp = zf + (size_t)d * CD + t * 4;
    atomicAdd(zp + 0, alpha * (v.x + w.x));
    atomicAdd(zp + 1, alpha * (v.y + w.y));
    atomicAdd(zp + 2, alpha * (v.z + w.z));
    atomicAdd(zp + 3, alpha * (v.w + w.w));
}

__global__ void pred_kernel(const float* __restrict__ ph,
                            const float* __restrict__ Wp2,
                            const float* __restrict__ bp2,
                            float* __restrict__ out)
{
    int p    = blockIdx.x * 8 + (threadIdx.x >> 5);
    int lane = threadIdx.x & 31;
    if (p >= CP) return;
    const float4* row = (const float4*)(ph + (size_t)p * CD);
    const float4* w   = (const float4*)Wp2;
    float s = 0.f;
#pragma unroll
    for (int i = 0; i < 4; i++) {
        float4 v  = row[lane + i * 32];
        float4 wv = w[lane + i * 32];
        s += v.x * wv.x + v.y * wv.y + v.z * wv.z + v.w * wv.w;
    }
#pragma unroll
    for (int o = 16; o; o >>= 1) s += __shfl_xor_sync(0xffffffffu, s, o);
    if (lane == 0) out[p] = s + bp2[0];
}

// ---------------------------------------------------------------------------
// Launch
// ---------------------------------------------------------------------------
extern "C" void kernel_launch(void* const* d_in, const int* in_sizes, int n_in,
                              void* d_out, int out_size)
{
    const float* n_f  = (const float*)d_in[0];
    const float* s_f  = (const float*)d_in[1];
    const float* We1  = (const float*)d_in[2];
    const float* be1  = (const float*)d_in[3];
    const float* We2  = (const float*)d_in[4];
    const float* be2  = (const float*)d_in[5];
    const float* Wa   = (const float*)d_in[6];
    const float* ba   = (const float*)d_in[7];
    const float* Wn   = (const float*)d_in[8];
    const float* bn   = (const float*)d_in[9];
    const float* Wp1  = (const float*)d_in[10];
    const float* bp1  = (const float*)d_in[11];
    const float* Wp2  = (const float*)d_in[12];
    const float* bp2  = (const float*)d_in[13];
    const int*   src  = (const int*)d_in[14];
    const int*   dst  = (const int*)d_in[15];
    const int*   pidx = (const int*)d_in[16];
    float* out = (float*)d_out;

    __half *hidHi, *hidLo, *w1hi, *w1lo, *w2hi, *w2lo;
    float *efP, *aP, *exP, *mP, *denP, *zfP, *newnP, *phP;
    cudaGetSymbolAddress((void**)&hidHi, g_hidhi);
    cudaGetSymbolAddress((void**)&hidLo, g_hidlo);
    cudaGetSymbolAddress((void**)&w1hi,  g_w1hi);
    cudaGetSymbolAddress((void**)&w1lo,  g_w1lo);
    cudaGetSymbolAddress((void**)&w2hi,  g_w2hi);
    cudaGetSymbolAddress((void**)&w2lo,  g_w2lo);
    cudaGetSymbolAddress((void**)&efP,   g_ef);
    cudaGetSymbolAddress((void**)&aP,    g_a);
    cudaGetSymbolAddress((void**)&exP,   g_ex);
    cudaGetSymbolAddress((void**)&mP,    g_m);
    cudaGetSymbolAddress((void**)&denP,  g_den);
    cudaGetSymbolAddress((void**)&zfP,   g_zf);
    cudaGetSymbolAddress((void**)&newnP, g_newn);
    cudaGetSymbolAddress((void**)&phP,   g_ph);

    cudaFuncSetAttribute(mma_gemm<0>, cudaFuncAttributeMaxDynamicSharedMemorySize, SMEM_MMA);
    cudaFuncSetAttribute(mma_gemm<1>, cudaFuncAttributeMaxDynamicSharedMemorySize, SMEM_MMA);

    // 0) weight prep (transpose + fp16 hi/lo split) and softmax init
    transpose_split<<<dim3(CH / 32, K1 / 32), dim3(32, 8)>>>(We1, w1hi, w1lo, K1, CH);
    transpose_split<<<dim3(CD / 32, CH / 32), dim3(32, 8)>>>(We2, w2hi, w2lo, CH, CD);
    init_kernel<<<(CN * CD + 255) / 256, 256>>>(mP, denP, zfP);

    // 1) hidden(hi/lo) = relu(concat(n_f[src], s_f, n_f[dst]) @ We1 + be1)   [E,1024]
    mma_gemm<0><<<dim3(CH / 128, CE / 128), 256, SMEM_MMA>>>(
        CH, K1, n_f, s_f, src, dst,
        nullptr, nullptr, w1hi, w1lo, be1, hidHi, hidLo, nullptr);

    // 2) e_f = hidden @ We2 + be2                                            [E,512]
    mma_gemm<1><<<dim3(CD / 128, CE / 128), 256, SMEM_MMA>>>(
        CD, CH, nullptr, nullptr, nullptr, nullptr,
        hidHi, hidLo, w2hi, w2lo, be2, nullptr, nullptr, efP);

    // 3-5) segment softmax + scatter
    edge_logit_kernel<<<CE / 8, 256>>>(efP, Wa, ba, dst, aP, mP);
    edge_exp_kernel<<<(CE + 255) / 256, 256>>>(aP, dst, mP, exP, denP);
    scatter_z_kernel<<<CE, 128>>>(n_f, efP, src, dst, exP, denP, zfP);

    // 6) new_n = concat(n_f, z_f) @ Wn + bn                                  [N,512]
    gemm128<3, false><<<dim3(CD / 128, (CN + 127) / 128), 256>>>(
        CN, CD, 2 * CD, n_f, nullptr, zfP, nullptr, nullptr, nullptr,
        Wn, bn, newnP);

    // 7) ph = relu(concat(new_n[src[pe]], s_f[pe], new_n[dst[pe]]) @ Wp1 + bp1)
    gemm128<2, true><<<dim3(CD / 128, (CP + 127) / 128), 256>>>(
        CP, CD, 2 * CD + CS, newnP, s_f, nullptr, src, dst, pidx,
        Wp1, bp1, phP);

    // 8) pred = ph @ Wp2 + bp2
    pred_kernel<<<CP / 8, 256>>>(phP, Wp2, bp2, out);
}